// round 16
// baseline (speedup 1.0000x reference)
#include <cuda_runtime.h>
#include <cuda_bf16.h>
#include <cstdint>
#include <math.h>

#define T_STEPS 1024
#define BATCH   64
#define UDIM    256
#define FDIM    128

// 64MB scratch for h[b][t][u] (device global: allowed, no runtime alloc)
__device__ float g_h[(size_t)BATCH * T_STEPS * UDIM];

// ---------------- helpers ----------------
__device__ __forceinline__ void fma2(unsigned long long &d, unsigned long long a, unsigned long long b) {
    asm("fma.rn.f32x2 %0, %1, %2, %0;" : "+l"(d) : "l"(a), "l"(b));
}
__device__ __forceinline__ float lo32(unsigned long long v){ return __uint_as_float((unsigned)(v & 0xffffffffull)); }
__device__ __forceinline__ float hi32(unsigned long long v){ return __uint_as_float((unsigned)(v >> 32)); }
__device__ __forceinline__ unsigned long long packf2(float lo, float hi){
    return (unsigned long long)__float_as_uint(lo) | ((unsigned long long)__float_as_uint(hi) << 32);
}
__device__ __forceinline__ uint32_t smem_u32(const void* p) {
    return (uint32_t)__cvta_generic_to_shared(p);
}
__device__ __forceinline__ uint32_t mapa_u32(uint32_t a, uint32_t peer) {
    uint32_t d;
    asm("mapa.shared::cluster.u32 %0, %1, %2;" : "=r"(d) : "r"(a), "r"(peer));
    return d;
}
__device__ __forceinline__ void mbar_init(uint32_t addr, uint32_t count) {
    asm volatile("mbarrier.init.shared.b64 [%0], %1;" :: "r"(addr), "r"(count) : "memory");
}
__device__ __forceinline__ void mbar_arrive_plain(uint32_t addr) {
    asm volatile("mbarrier.arrive.shared::cta.b64 _, [%0];" :: "r"(addr) : "memory");
}
__device__ __forceinline__ void mbar_expect_tx(uint32_t addr, uint32_t bytes) {
    asm volatile("mbarrier.arrive.expect_tx.shared::cta.b64 _, [%0], %1;"
                 :: "r"(addr), "r"(bytes) : "memory");
}
// cta-scope acquire: st.async deliveries complete at the destination smem
// before the tx counts, so cluster-scope acquire is unnecessary.
__device__ __forceinline__ void mbar_wait(uint32_t addr, uint32_t parity) {
    asm volatile(
        "{\n\t"
        ".reg .pred P;\n\t"
        "WAIT_%=:\n\t"
        "mbarrier.try_wait.parity.acquire.cta.shared::cta.b64 P, [%0], %1, 0x989680;\n\t"
        "@P bra DONE_%=;\n\t"
        "bra WAIT_%=;\n\t"
        "DONE_%=:\n\t"
        "}"
        :: "r"(addr), "r"(parity) : "memory");
}
// fused data+signal: store 4B into (cluster) smem and complete_tx on the
// mbarrier co-located in the SAME destination CTA. One transaction.
__device__ __forceinline__ void st_async_f32(uint32_t daddr, float v, uint32_t dmbar) {
    asm volatile("st.async.shared::cluster.mbarrier::complete_tx::bytes.f32 [%0], %1, [%2];"
                 :: "r"(daddr), "f"(v), "r"(dmbar) : "memory");
}
// branchless tanh: 1 - 2/(exp(2x)+1), ex2.approx + rcp.approx (~1e-7 abs err)
__device__ __forceinline__ float fast_tanh(float x) {
    float z = x * 2.8853900817779268f;   // 2*log2(e)
    float e;
    asm("ex2.approx.f32 %0, %1;" : "=f"(e) : "f"(z));
    float d = e + 1.0f;
    float r;
    asm("rcp.approx.f32 %0, %1;" : "=f"(r) : "f"(d));
    return fmaf(-2.0f, r, 1.0f);
}

// state buffer layout: quarter q (64 cols) padded by 16B so the 4 per-warp
// broadcast groups (one per K-quarter) hit disjoint bank sets.
#define SBUF_STRIDE 272
#define PAR_B  ((uint32_t)(SBUF_STRIDE * 4))      // bytes per parity slot
#define BAT_B  ((uint32_t)(2 * SBUF_STRIDE * 4))  // bytes per batch
__device__ __forceinline__ int sidx4(int c){ return c + ((c >> 6) << 2); }

// ============================================================
// Phase 1: g_h[b][t][u] = sum_f inputs[b,t,f] * R[f,u]
// ============================================================
__global__ __launch_bounds__(256)
void p1_gemm(const float* __restrict__ x, const float* __restrict__ R) {
    extern __shared__ unsigned char smraw[];
    float* xs = (float*)smraw;                                          // 32KB
    unsigned long long* Rp = (unsigned long long*)(smraw + 64*128*4);   // 64KB

    const int tid = threadIdx.x;
    const int c = blockIdx.x;
    const int rowblk = c >> 1, uh = c & 1;
    const int m0 = rowblk * 64, ub = uh * 128;

    {
        const float4* xg = (const float4*)(x + (size_t)m0 * FDIM);
        float4* xs4 = (float4*)xs;
        #pragma unroll
        for (int i = 0; i < 8; i++) xs4[tid + 256*i] = xg[tid + 256*i];
    }
    for (int i = tid; i < 64*128; i += 256) {
        int k2 = i >> 7; int u = (i & 127) + ub;
        Rp[i] = packf2(R[(size_t)(2*k2) * UDIM + u], R[(size_t)(2*k2+1) * UDIM + u]);
    }
    __syncthreads();

    const int cg = tid & 31, tr = tid >> 5;
    const int u0 = cg * 4, r0 = tr * 8;

    unsigned long long acc[8][4];
    #pragma unroll
    for (int a = 0; a < 8; a++)
        #pragma unroll
        for (int bb = 0; bb < 4; bb++) acc[a][bb] = 0ULL;

    #pragma unroll 8
    for (int k2 = 0; k2 < 64; k2++) {
        const ulonglong2* rp2 = (const ulonglong2*)(Rp + k2*128 + u0);
        ulonglong2 v0 = rp2[0], v1 = rp2[1];
        #pragma unroll
        for (int rr = 0; rr < 8; rr++) {
            unsigned long long xp = *(const unsigned long long*)(xs + (r0+rr)*FDIM + 2*k2);
            fma2(acc[rr][0], xp, v0.x);
            fma2(acc[rr][1], xp, v0.y);
            fma2(acc[rr][2], xp, v1.x);
            fma2(acc[rr][3], xp, v1.y);
        }
    }

    #pragma unroll
    for (int rr = 0; rr < 8; rr++) {
        int m = m0 + r0 + rr;   // m = b*1024 + t -> [B][T][U] directly
        float4 o;
        o.x = lo32(acc[rr][0]) + hi32(acc[rr][0]);
        o.y = lo32(acc[rr][1]) + hi32(acc[rr][1]);
        o.z = lo32(acc[rr][2]) + hi32(acc[rr][2]);
        o.w = lo32(acc[rr][3]) + hi32(acc[rr][3]);
        *(float4*)(g_h + (size_t)m * UDIM + ub + u0) = o;
    }
}

// ============================================================
// Phase 2: recurrence, 2-batch pipeline, 512 THREADS (4 warps/SMSP).
// 32 clusters x 2 CTAs; cluster c handles batches 2c, 2c+1.
// Thread map (warp w=0..15, lane l): col j = w*8 + (l&7) (0..127),
// quarter q = l>>3, K range [q*64, q*64+64). ONE column per thread:
// 16 LDS.128 -> 32 FFMA2 per batch-step. W = 32 u64 = 64 regs/thread.
// Reduce over q: shfl.xor(8) + shfl.xor(16); all 4 q-lanes hold the sum.
// Epilogue (1 store per thread per batch): q0 -> own st.async, q1 -> peer
// st.async, q2 -> b0 output STG, q3 -> b1 output STG.
// ILP ordering from R15: wait0/FMA0 -> wait1/FMA1 -> tail0 -> tail1.
// Protocol unchanged: per-batch mbar, 1024B expect_tx, parity t&1,
// phase-0 bootstrap arrive, cta-scope acquire.
// ============================================================
__global__ __launch_bounds__(512, 1) __cluster_dims__(2, 1, 1)
void p2_rnn(const float* __restrict__ W, const float* __restrict__ bias,
            const float* __restrict__ x0, float* __restrict__ out) {
    __shared__ __align__(16) float sbuf[2][2][SBUF_STRIDE];  // [batch][parity][state]
    __shared__ __align__(8) unsigned long long mbar[2];

    const int tid  = threadIdx.x;
    uint32_t rank;
    asm("mov.u32 %0, %%cluster_ctarank;" : "=r"(rank));
    const int c    = blockIdx.x >> 1;       // cluster index
    const int b0   = 2 * c, b1 = 2 * c + 1;
    const int w    = tid >> 5;
    const int l    = tid & 31;
    const int j    = w * 8 + (l & 7);                // local column 0..127
    const int jg   = (int)rank * 128 + j;            // global output column
    const int k0   = (l >> 3) * 64;                  // K-quarter start

    // W column segment, quarter-K, packed f32x2: 32 u64 = 64 regs
    unsigned long long wp[32];
    #pragma unroll
    for (int m = 0; m < 32; m++) {
        wp[m] = packf2(W[(size_t)(k0 + 2*m)     * UDIM + jg],
                       W[(size_t)(k0 + 2*m + 1) * UDIM + jg]);
    }

    const float* hp0 = g_h + (size_t)b0 * T_STEPS * UDIM + jg;
    const float* hp1 = g_h + (size_t)b1 * T_STEPS * UDIM + jg;
    float* ob0 = out + (size_t)b0 * UDIM + jg;
    float* ob1 = out + (size_t)b1 * UDIM + jg;
    const float bias_j = bias[jg];
    float h0_0 = hp0[0], h1_0 = hp0[UDIM];
    float h0_1 = hp1[0], h1_1 = hp1[UDIM];

    if (tid < UDIM) {
        float v = x0[tid];
        sbuf[0][0][sidx4(tid)] = v;
        sbuf[1][0][sidx4(tid)] = v;
    }
    if (tid == 0) {
        mbar_init(smem_u32(&mbar[0]), 1);
        mbar_init(smem_u32(&mbar[1]), 1);
        mbar_arrive_plain(smem_u32(&mbar[0]));   // complete phase 0
        mbar_arrive_plain(smem_u32(&mbar[1]));
    }
    __syncthreads();
    asm volatile("barrier.cluster.arrive.aligned;" ::: "memory");
    asm volatile("barrier.cluster.wait.aligned;"   ::: "memory");

    const uint32_t m0loc = smem_u32(&mbar[0]);
    const uint32_t m1loc = smem_u32(&mbar[1]);
    const uint32_t pr    = rank ^ 1u;
    const uint32_t omb0  = mapa_u32(m0loc, rank);
    const uint32_t pmb0  = mapa_u32(m0loc, pr);
    const uint32_t omb1  = mapa_u32(m1loc, rank);
    const uint32_t pmb1  = mapa_u32(m1loc, pr);
    const uint32_t osb   = mapa_u32(smem_u32(&sbuf[0][0][0]), rank);
    const uint32_t psb   = mapa_u32(smem_u32(&sbuf[0][0][0]), pr);
    const uint32_t doff  = (uint32_t)sidx4(jg) * 4u;

    #pragma unroll 2
    for (int t = 0; t < T_STEPS; t++) {
        const int p = t & 1;
        const uint32_t np  = (uint32_t)(p ^ 1);
        const uint32_t par = (uint32_t)(t & 1);

        // prefetch h for t+2 (independent of the chain)
        float h2_0 = 0.f, h2_1 = 0.f;
        if (t + 2 < T_STEPS) {
            h2_0 = __ldcs(hp0 + (size_t)(t + 2) * UDIM);
            h2_1 = __ldcs(hp1 + (size_t)(t + 2) * UDIM);
        }

        // ---- batch 0: wait + FMA issue burst ----
        mbar_wait(m0loc, par);
        if (tid == 0) mbar_expect_tx(m0loc, 1024);
        unsigned long long a0_0 = 0ULL, a1_0 = 0ULL, a2_0 = 0ULL, a3_0 = 0ULL;
        {
            const float* sb = &sbuf[0][p][sidx4(k0)];
            #pragma unroll
            for (int i = 0; i < 8; i++) {
                ulonglong2 s0 = *(const ulonglong2*)(sb + 8*i);
                ulonglong2 s1 = *(const ulonglong2*)(sb + 8*i + 4);
                fma2(a0_0, s0.x, wp[4*i + 0]);
                fma2(a1_0, s0.y, wp[4*i + 1]);
                fma2(a2_0, s1.x, wp[4*i + 2]);
                fma2(a3_0, s1.y, wp[4*i + 3]);
            }
        }

        // ---- batch 1: wait (in b0's FMA shadow) + FMA issue burst ----
        mbar_wait(m1loc, par);
        if (tid == 0) mbar_expect_tx(m1loc, 1024);
        unsigned long long a0_1 = 0ULL, a1_1 = 0ULL, a2_1 = 0ULL, a3_1 = 0ULL;
        {
            const float* sb = &sbuf[1][p][sidx4(k0)];
            #pragma unroll
            for (int i = 0; i < 8; i++) {
                ulonglong2 s0 = *(const ulonglong2*)(sb + 8*i);
                ulonglong2 s1 = *(const ulonglong2*)(sb + 8*i + 4);
                fma2(a0_1, s0.x, wp[4*i + 0]);
                fma2(a1_1, s0.y, wp[4*i + 1]);
                fma2(a2_1, s1.x, wp[4*i + 2]);
                fma2(a3_1, s1.y, wp[4*i + 3]);
            }
        }

        // ---- batch 0 tail: latencies hide under b1's FMA drain ----
        float val0;
        {
            float pa = ((lo32(a0_0) + hi32(a0_0)) + (lo32(a1_0) + hi32(a1_0)))
                     + ((lo32(a2_0) + hi32(a2_0)) + (lo32(a3_0) + hi32(a3_0)));
            pa += __shfl_xor_sync(0xffffffffu, pa, 8);
            pa += __shfl_xor_sync(0xffffffffu, pa, 16);
            val0 = fast_tanh(h0_0 + pa + bias_j);
        }
        if (l < 8) {
            st_async_f32(osb + np * PAR_B + doff, val0, omb0);
        } else if (l < 16) {
            st_async_f32(psb + np * PAR_B + doff, val0, pmb0);
        }

        // ---- batch 1 tail ----
        float val1;
        {
            float pa = ((lo32(a0_1) + hi32(a0_1)) + (lo32(a1_1) + hi32(a1_1)))
                     + ((lo32(a2_1) + hi32(a2_1)) + (lo32(a3_1) + hi32(a3_1)));
            pa += __shfl_xor_sync(0xffffffffu, pa, 8);
            pa += __shfl_xor_sync(0xffffffffu, pa, 16);
            val1 = fast_tanh(h0_1 + pa + bias_j);
        }
        if (l < 8) {
            st_async_f32(osb + BAT_B + np * PAR_B + doff, val1, omb1);
        } else if (l < 16) {
            st_async_f32(psb + BAT_B + np * PAR_B + doff, val1, pmb1);
        } else if (l < 24) {
            ob0[(size_t)t * BATCH * UDIM] = val0;   // [T][B][U]
        } else {
            ob1[(size_t)t * BATCH * UDIM] = val1;
        }

        h0_0 = h1_0; h1_0 = h2_0;
        h0_1 = h1_1; h1_1 = h2_1;
    }

    asm volatile("barrier.cluster.arrive.aligned;" ::: "memory");
    asm volatile("barrier.cluster.wait.aligned;"   ::: "memory");
}

extern "C" void kernel_launch(void* const* d_in, const int* in_sizes, int n_in,
                              void* d_out, int out_size) {
    const float* x    = (const float*)d_in[0];  // [B, T, F]
    const float* R    = (const float*)d_in[1];  // [F, U]
    const float* W    = (const float*)d_in[2];  // [U, U]
    const float* bias = (const float*)d_in[3];  // [U]
    const float* x0   = (const float*)d_in[4];  // [U]
    float* out = (float*)d_out;                 // [T, B, U]

    cudaFuncSetAttribute(p1_gemm, cudaFuncAttributeMaxDynamicSharedMemorySize, 98304);
    p1_gemm<<<2048, 256, 98304>>>(x, R);
    p2_rnn<<<64, 512>>>(W, bias, x0, out);
}